// round 12
// baseline (speedup 1.0000x reference)
#include <cuda_runtime.h>
#include <cuda_bf16.h>
#include <cstddef>
#include <cstdint>

// ---------------------------------------------------------------------------
// StyleGAN2 block via legacy tensor cores (mma.sync m16n8k16 bf16, base PTX).
// Conv as implicit GEMM; bf16 hi/lo split packed into K (3 MMAs), ~1e-5.
// R12 vs R11: double-buffered B slab with buildB sliced + interleaved into the
// MMA stages (tensor pipe no longer idles on B construction); one barrier per
// stage; launch order makes conv the 6th launch so ncu -s 5 captures it.
// ---------------------------------------------------------------------------

#define BATCH 8
#define CH    256
#define HW    128
#define LAT   512

__device__ float g_mid[(size_t)BATCH * CH * HW * HW];   // conv1 output
__device__ float g_s1[BATCH * CH];
__device__ float g_s2[BATCH * CH];
__device__ float g_s3[BATCH * CH];
__device__ float g_r1[BATCH * CH];
__device__ float g_r2[BATCH * CH];
__device__ float g_wq1[CH * CH];
__device__ float g_wq2[CH * CH];
// rearranged weights: 96 stages x [kx(3)][oc(128)][40 slots] bf16  (2.95MB)
#define WA_STAGE_HALFS 15360            // 3*128*40
#define WA_HALFS ((size_t)96 * WA_STAGE_HALFS)
__device__ unsigned short g_wa1[WA_HALFS];
__device__ unsigned short g_wa2[WA_HALFS];

// ---------------- helpers ----------------
__device__ __forceinline__ float warp_sum(float v) {
    #pragma unroll
    for (int m = 16; m > 0; m >>= 1) v += __shfl_xor_sync(0xffffffffu, v, m);
    return v;
}
__device__ __forceinline__ uint32_t smem_u32(const void* p) {
    uint32_t a;
    asm("{ .reg .u64 t; cvta.to.shared.u64 t, %1; cvt.u32.u64 %0, t; }"
        : "=r"(a) : "l"(p));
    return a;
}
__device__ __forceinline__ void cp_async16(uint32_t smem, const void* gmem) {
    asm volatile("cp.async.cg.shared.global [%0], [%1], 16;" :: "r"(smem), "l"(gmem));
}
#define CP_COMMIT() asm volatile("cp.async.commit_group;" ::: "memory")
#define CP_WAIT0()  asm volatile("cp.async.wait_group 0;" ::: "memory")

#define LDM_X4(r, addr) \
    asm volatile("ldmatrix.sync.aligned.m8n8.x4.shared.b16 {%0,%1,%2,%3}, [%4];" \
        : "=r"((r)[0]), "=r"((r)[1]), "=r"((r)[2]), "=r"((r)[3]) : "r"(addr))
// NON-trans x2: rows addressed by lanes 0-15; lane l gets M[l/4][2*(l%4)..+1]
#define LDM_X2(r0, r1, addr) \
    asm volatile("ldmatrix.sync.aligned.m8n8.x2.shared.b16 {%0,%1}, [%2];" \
        : "=r"(r0), "=r"(r1) : "r"(addr))
#define MMA_BF16(c, a, b0, b1) \
    asm volatile("mma.sync.aligned.m16n8k16.row.col.f32.bf16.bf16.f32 " \
        "{%0,%1,%2,%3}, {%4,%5,%6,%7}, {%8,%9}, {%0,%1,%2,%3};" \
        : "+f"((c)[0]), "+f"((c)[1]), "+f"((c)[2]), "+f"((c)[3]) \
        : "r"((a)[0]), "r"((a)[1]), "r"((a)[2]), "r"((a)[3]), "r"(b0), "r"(b1))

// ---------------- small kernels ----------------
__global__ void styles_kernel(const float* __restrict__ wvec,
                              const float* __restrict__ Aw,
                              const float* __restrict__ Ab,
                              float* __restrict__ outp) {
    const int b = blockIdx.y, wid = threadIdx.x >> 5, lane = threadIdx.x & 31;
    const int o = blockIdx.x * 8 + wid;
    const float* wp = wvec + b * LAT;
    const float* ap = Aw + (size_t)o * LAT;
    float acc = 0.f;
    #pragma unroll
    for (int it = 0; it < LAT / 32; it++) {
        int k = lane + 32 * it;
        acc += __ldg(&wp[k]) * __ldg(&ap[k]);
    }
    acc = warp_sum(acc);
    if (lane == 0) outp[b * CH + o] = acc + __ldg(&Ab[o]);
}
__global__ void wsq_kernel(const float* __restrict__ W, float* __restrict__ wq) {
    const int oi = blockIdx.x * 256 + threadIdx.x;
    const float* wp = W + (size_t)oi * 9;
    float s = 0.f;
    #pragma unroll
    for (int t = 0; t < 9; t++) { float v = __ldg(&wp[t]); s += v * v; }
    wq[oi] = s;
}
__global__ void rsigma_kernel(const float* __restrict__ style,
                              const float* __restrict__ wq,
                              float* __restrict__ rsig) {
    __shared__ float ss[CH];
    const int b = blockIdx.x, tid = threadIdx.x, wid = tid >> 5, lane = tid & 31;
    { float s = style[b * CH + tid]; ss[tid] = s * s; }
    __syncthreads();
    const int o0 = blockIdx.y * 32 + wid * 4;
    #pragma unroll
    for (int j = 0; j < 4; j++) {
        const int o = o0 + j;
        const float* qp = wq + (size_t)o * CH;
        float acc = 0.f;
        #pragma unroll
        for (int it = 0; it < CH / 32; it++)
            acc += ss[lane + 32 * it] * __ldg(&qp[lane + 32 * it]);
        acc = warp_sum(acc);
        if (lane == 0) rsig[b * CH + o] = rsqrtf(acc + 1e-8f);
    }
}

// ---------------- weight prep: W[256,256,3,3] -> ldmatrix-ready hi/lo -------
// stage st = (ocb*16 + chunk)*3 + ky; layout [kx][oc(128)][40] bf16 (80B rows)
// slots [0,16): Wh(ci = chunk*16+s), [16,32): Wl, [32,40): pad.
__global__ void wprep_kernel(const float* __restrict__ W,
                             unsigned short* __restrict__ wa) {
    size_t e = (size_t)blockIdx.x * 256 + threadIdx.x;   // < 96*15360
    int st = (int)(e / WA_STAGE_HALFS);
    int r  = (int)(e - (size_t)st * WA_STAGE_HALFS);
    int kx = r / 5120;  r -= kx * 5120;
    int oc = r / 40;
    int slot = r - oc * 40;
    int ocb = st / 48, s2 = st - ocb * 48;
    int chunk = s2 / 3, ky = s2 - chunk * 3;
    unsigned short outv = 0;
    if (slot < 32) {
        int ci = chunk * 16 + (slot & 15);
        float w = __ldg(&W[((size_t)(ocb * 128 + oc) * CH + ci) * 9 + ky * 3 + kx]);
        __nv_bfloat16 wh = __float2bfloat16(w);
        if (slot < 16) outv = __bfloat16_as_ushort(wh);
        else outv = __bfloat16_as_ushort(__float2bfloat16(w - __bfloat162float(wh)));
    }
    wa[e] = outv;
}

// ---------------- tensor-core conv kernel -----------------------------------
// CTA: 128 oc x 256 px (2 image rows). 256 threads = 8 warps (warp 64x64).
// smem: [0,1024) style | B double buffer 2 x 41600 (520 rows x 80B) |
//       A double buffer 2 x 30720
#define SMB_OFF   1024
#define B_SLAB    41600
#define SMA_OFF   (SMB_OFF + 2 * B_SLAB)        // 84224
#define A_STAGE   30720
#define CONV_SMEM (SMA_OFF + 2 * A_STAGE)       // 145664

__global__ __launch_bounds__(256, 1)
void conv_mma_kernel(const float* __restrict__ in,
                     const unsigned short* __restrict__ wa,
                     const float* __restrict__ style,
                     const float* __restrict__ rsig,
                     const float* __restrict__ bias,
                     const float* __restrict__ ns,
                     const float* __restrict__ noise,
                     float* __restrict__ outp) {
    extern __shared__ unsigned char sm[];
    float* s_style = (float*)sm;
    const uint32_t smBu = smem_u32(sm + SMB_OFF);
    const uint32_t smAu = smem_u32(sm + SMA_OFF);

    const int tid  = threadIdx.x;
    const int wid  = tid >> 5;
    const int lane = tid & 31;
    const int wm   = wid & 1;        // oc half
    const int wn   = wid >> 1;       // 0..3 -> (row, x-half)
    const int y0   = blockIdx.x * 2;
    const int ocb  = blockIdx.y;
    const int b    = blockIdx.z;

    if (tid < CH) s_style[tid] = __ldg(&style[b * CH + tid]);

    float acc[4][8][4];
    #pragma unroll
    for (int m = 0; m < 4; m++)
        #pragma unroll
        for (int n = 0; n < 8; n++)
            #pragma unroll
            for (int k = 0; k < 4; k++) acc[m][n][k] = 0.f;

    // lane-level ldmatrix address components
    const uint32_t aLane = (uint32_t)(wm * 64 + (lane & 15)) * 80 + ((lane >> 4) * 16);
    const uint32_t bLane = (uint32_t)(lane & 7) * 80 + (((lane >> 3) & 1) * 16);

    const unsigned short* waBase = wa + (size_t)ocb * 48 * WA_STAGE_HALFS;

    auto stageA = [&](int st) {
        const unsigned char* src = (const unsigned char*)(waBase + (size_t)st * WA_STAGE_HALFS);
        uint32_t dst = smAu + (uint32_t)(st & 1) * A_STAGE;
        for (int i = tid; i < 1920; i += 256)
            cp_async16(dst + i * 16, src + (size_t)i * 16);
    };
    // build slice [e0,e1) of B(chunk) into buffer pb
    auto buildB = [&](int chunk, int pb, int e0, int e1) {
        unsigned char* smB = sm + SMB_OFF + pb * B_SLAB;
        for (int e = e0 + tid; e < e1; e += 256) {
            int cl = e / 520;  int r = e - cl * 520;
            int rr = r / 130;  int pxi = r - rr * 130;
            int yi = y0 - 1 + rr, xi = pxi - 1;
            int ci = chunk * 16 + cl * 2;
            float v0 = 0.f, v1 = 0.f;
            if ((unsigned)yi < (unsigned)HW && (unsigned)xi < (unsigned)HW) {
                size_t base = ((size_t)(b * CH + ci) << 14) + (yi << 7) + xi;
                v0 = __ldg(&in[base]) * s_style[ci];
                v1 = __ldg(&in[base + (size_t)(1 << 14)]) * s_style[ci + 1];
            }
            __nv_bfloat16 h0 = __float2bfloat16(v0), h1 = __float2bfloat16(v1);
            __nv_bfloat16 l0 = __float2bfloat16(v0 - __bfloat162float(h0));
            __nv_bfloat16 l1 = __float2bfloat16(v1 - __bfloat162float(h1));
            uint32_t hh = ((uint32_t)__bfloat16_as_ushort(h1) << 16) | __bfloat16_as_ushort(h0);
            uint32_t ll = ((uint32_t)__bfloat16_as_ushort(l1) << 16) | __bfloat16_as_ushort(l0);
            int rp = rr * 130 + pxi;
            *(uint32_t*)(smB + rp * 80 + cl * 4)      = hh;
            *(uint32_t*)(smB + rp * 80 + 32 + cl * 4) = ll;
        }
    };

    stageA(0); CP_COMMIT();
    __syncthreads();                 // style visible to all warps
    buildB(0, 0, 0, 4160);           // full build of chunk 0 into buffer 0

    #pragma unroll 1
    for (int st = 0; st < 48; st++) {
        const int chunk = st / 3, ky = st - chunk * 3;
        const int pb = chunk & 1;
        CP_WAIT0();                  // A(st) landed
        __syncthreads();             // A(st)+B visible; old-buffer readers done
        if (st + 1 < 48) { stageA(st + 1); CP_COMMIT(); }

        const uint32_t aBuf = smAu + (uint32_t)(st & 1) * A_STAGE;
        const uint32_t bBuf = smBu + (uint32_t)pb * B_SLAB;
        const int rr  = (wn >> 1) + ky;       // B slab image-row
        const int x0w = (wn & 1) * 64;

        #pragma unroll 1
        for (int kx = 0; kx < 3; kx++) {
            uint32_t a0[4][4], a1[4][4];      // Ah frags, Al frags
            #pragma unroll
            for (int m = 0; m < 4; m++) {
                uint32_t aa = aBuf + (uint32_t)kx * 10240 + (uint32_t)m * (16 * 80) + aLane;
                LDM_X4(a0[m], aa);
                LDM_X4(a1[m], aa + 32);
            }
            const uint32_t bRow0 = bBuf + (uint32_t)(rr * 130 + x0w + kx) * 80 + bLane;
            #pragma unroll
            for (int n = 0; n < 8; n++) {
                uint32_t ba = bRow0 + (uint32_t)n * (8 * 80);
                uint32_t bh0, bh1, bl0, bl1;
                LDM_X2(bh0, bh1, ba);         // Bh (k 0-15)
                LDM_X2(bl0, bl1, ba + 32);    // Bl
                #pragma unroll
                for (int m = 0; m < 4; m++) MMA_BF16(acc[m][n], a0[m], bh0, bh1);
                #pragma unroll
                for (int m = 0; m < 4; m++) MMA_BF16(acc[m][n], a1[m], bh0, bh1);
                #pragma unroll
                for (int m = 0; m < 4; m++) MMA_BF16(acc[m][n], a0[m], bl0, bl1);
            }
        }

        // interleaved build of B(chunk+1) into the other buffer, one slice
        // per ky stage; first read is at stage 3(chunk+1), after a barrier.
        if (chunk + 1 < 16) {
            const int e0 = (ky == 0) ? 0 : (ky == 1 ? 1387 : 2774);
            const int e1 = (ky == 0) ? 1387 : (ky == 1 ? 2774 : 4160);
            buildB(chunk + 1, 1 - pb, e0, e1);
        }
    }

    // ---- epilogue: demod + noise + bias + leaky relu ----
    const float nsv = __ldg(&ns[0]);
    const int y = y0 + (wn >> 1);
    #pragma unroll
    for (int m = 0; m < 4; m++) {
        const int oc0 = ocb * 128 + wm * 64 + m * 16 + (lane >> 2);
        const float rs0 = __ldg(&rsig[b * CH + oc0]);
        const float rs1 = __ldg(&rsig[b * CH + oc0 + 8]);
        const float bj0 = __ldg(&bias[oc0]);
        const float bj1 = __ldg(&bias[oc0 + 8]);
        float* op0 = outp + ((size_t)(b * CH + oc0) << 14) + (y << 7);
        float* op1 = op0 + ((size_t)8 << 14);
        #pragma unroll
        for (int n = 0; n < 8; n++) {
            const int x = (wn & 1) * 64 + n * 8 + 2 * (lane & 3);
            float2 nz = *(const float2*)(noise + ((size_t)b << 14) + (y << 7) + x);
            float v0 = acc[m][n][0] * rs0 + nsv * nz.x + bj0;
            float v1 = acc[m][n][1] * rs0 + nsv * nz.y + bj0;
            float v2 = acc[m][n][2] * rs1 + nsv * nz.x + bj1;
            float v3 = acc[m][n][3] * rs1 + nsv * nz.y + bj1;
            v0 = (v0 > 0.f) ? v0 : 0.2f * v0;
            v1 = (v1 > 0.f) ? v1 : 0.2f * v1;
            v2 = (v2 > 0.f) ? v2 : 0.2f * v2;
            v3 = (v3 > 0.f) ? v3 : 0.2f * v3;
            *(float2*)(op0 + x) = make_float2(v0, v1);
            *(float2*)(op1 + x) = make_float2(v2, v3);
        }
    }
}

// ---------------- RGB 1x1 modulated conv (no demod) ------------------------
__global__ void rgb_kernel(const float* __restrict__ out2,
                           const float* __restrict__ W3,
                           const float* __restrict__ style3,
                           float* __restrict__ rgb) {
    __shared__ float cf[3][CH];
    const int y = blockIdx.x, b = blockIdx.y, tid = threadIdx.x;
    for (int e = tid; e < 3 * CH; e += 128) {
        int rr = e >> 8, o = e & 255;
        cf[rr][o] = __ldg(&W3[rr * CH + o]) * style3[b * CH + o];
    }
    __syncthreads();
    const int x = tid;
    float a0 = 0.f, a1 = 0.f, a2 = 0.f;
    const float* base = out2 + ((size_t)(b * CH) << 14) + (y << 7) + x;
    #pragma unroll 8
    for (int o = 0; o < CH; o++) {
        float v = base[(size_t)o << 14];
        a0 += cf[0][o] * v; a1 += cf[1][o] * v; a2 += cf[2][o] * v;
    }
    const size_t px = ((size_t)y << 7) + x;
    rgb[((size_t)(b * 3 + 0) << 14) + px] = a0;
    rgb[((size_t)(b * 3 + 1) << 14) + px] = a1;
    rgb[((size_t)(b * 3 + 2) << 14) + px] = a2;
}

// ---------------------------------------------------------------------------
extern "C" void kernel_launch(void* const* d_in, const int* in_sizes, int n_in,
                              void* d_out, int out_size) {
    (void)in_sizes; (void)n_in; (void)out_size;
    const float* fm     = (const float*)d_in[0];
    const float* wv     = (const float*)d_in[1];
    const float* noise1 = (const float*)d_in[2];
    const float* noise2 = (const float*)d_in[3];
    const float* A1w    = (const float*)d_in[4];
    const float* A1b    = (const float*)d_in[5];
    const float* A2w    = (const float*)d_in[6];
    const float* A2b    = (const float*)d_in[7];
    const float* A3w    = (const float*)d_in[8];
    const float* A3b    = (const float*)d_in[9];
    const float* W1     = (const float*)d_in[10];
    const float* W2     = (const float*)d_in[11];
    const float* W3     = (const float*)d_in[12];
    const float* ns1    = (const float*)d_in[13];
    const float* ns2    = (const float*)d_in[14];
    const float* b1     = (const float*)d_in[15];
    const float* b2     = (const float*)d_in[16];

    float* out = (float*)d_out;
    float* rgb = out + (size_t)BATCH * CH * HW * HW;

    void *p_mid,*p_s1,*p_s2,*p_s3,*p_r1,*p_r2,*p_q1,*p_q2,*p_a1,*p_a2;
    cudaGetSymbolAddress(&p_mid, g_mid);
    cudaGetSymbolAddress(&p_s1, g_s1);
    cudaGetSymbolAddress(&p_s2, g_s2);
    cudaGetSymbolAddress(&p_s3, g_s3);
    cudaGetSymbolAddress(&p_r1, g_r1);
    cudaGetSymbolAddress(&p_r2, g_r2);
    cudaGetSymbolAddress(&p_q1, g_wq1);
    cudaGetSymbolAddress(&p_q2, g_wq2);
    cudaGetSymbolAddress(&p_a1, g_wa1);
    cudaGetSymbolAddress(&p_a2, g_wa2);
    float* mid = (float*)p_mid;
    float* s1 = (float*)p_s1; float* s2 = (float*)p_s2; float* s3 = (float*)p_s3;
    float* r1 = (float*)p_r1; float* r2 = (float*)p_r2;
    float* q1 = (float*)p_q1; float* q2 = (float*)p_q2;
    unsigned short* wa1 = (unsigned short*)p_a1;
    unsigned short* wa2 = (unsigned short*)p_a2;

    cudaFuncSetAttribute(conv_mma_kernel,
                         cudaFuncAttributeMaxDynamicSharedMemorySize, CONV_SMEM);

    dim3 cgrid(HW / 2, 2, BATCH);   // 64 row-pairs, 2 oc halves, 8 batches

    // Launch order: conv1 is the 6th launch so ncu -s 5 -c 1 profiles it.
    styles_kernel<<<dim3(CH / 8, BATCH), 256>>>(wv, A1w, A1b, s1);    // 1
    styles_kernel<<<dim3(CH / 8, BATCH), 256>>>(wv, A2w, A2b, s2);    // 2
    wsq_kernel<<<CH * CH / 256, 256>>>(W1, q1);                       // 3
    rsigma_kernel<<<dim3(BATCH, CH / 32), 256>>>(s1, q1, r1);         // 4
    wprep_kernel<<<(int)(WA_HALFS / 256), 256>>>(W1, wa1);            // 5
    conv_mma_kernel<<<cgrid, 256, CONV_SMEM>>>(fm, wa1, s1, r1, b1,   // 6
                                               ns1, noise1, mid);
    styles_kernel<<<dim3(CH / 8, BATCH), 256>>>(wv, A3w, A3b, s3);
    wsq_kernel<<<CH * CH / 256, 256>>>(W2, q2);
    rsigma_kernel<<<dim3(BATCH, CH / 32), 256>>>(s2, q2, r2);
    wprep_kernel<<<(int)(WA_HALFS / 256), 256>>>(W2, wa2);
    conv_mma_kernel<<<cgrid, 256, CONV_SMEM>>>(mid, wa2, s2, r2, b2, ns2, noise2, out);
    rgb_kernel<<<dim3(HW, BATCH), 128>>>(out, W3, s3, rgb);
}

// round 13
// speedup vs baseline: 1.1562x; 1.1562x over previous
#include <cuda_runtime.h>
#include <cuda_bf16.h>
#include <cstddef>
#include <cstdint>

// ---------------------------------------------------------------------------
// StyleGAN2 block via legacy tensor cores (mma.sync m16n8k16 bf16, base PTX).
// Conv as implicit GEMM; bf16 hi/lo split packed into K (3 MMAs), ~1e-5.
// R13 vs R11: CTA halved to 128 threads / 1 image row -> 2 CTAs per SM
// (reg-limited before), so one CTA's barriers/buildB hide under the other's
// MMAs. MMA core, layouts and summation order identical to R11.
// ---------------------------------------------------------------------------

#define BATCH 8
#define CH    256
#define HW    128
#define LAT   512

__device__ float g_mid[(size_t)BATCH * CH * HW * HW];   // conv1 output
__device__ float g_s1[BATCH * CH];
__device__ float g_s2[BATCH * CH];
__device__ float g_s3[BATCH * CH];
__device__ float g_r1[BATCH * CH];
__device__ float g_r2[BATCH * CH];
__device__ float g_wq1[CH * CH];
__device__ float g_wq2[CH * CH];
// rearranged weights: 96 stages x [kx(3)][oc(128)][40 slots] bf16  (2.95MB)
#define WA_STAGE_HALFS 15360            // 3*128*40
#define WA_HALFS ((size_t)96 * WA_STAGE_HALFS)
__device__ unsigned short g_wa1[WA_HALFS];
__device__ unsigned short g_wa2[WA_HALFS];

// ---------------- helpers ----------------
__device__ __forceinline__ float warp_sum(float v) {
    #pragma unroll
    for (int m = 16; m > 0; m >>= 1) v += __shfl_xor_sync(0xffffffffu, v, m);
    return v;
}
__device__ __forceinline__ uint32_t smem_u32(const void* p) {
    uint32_t a;
    asm("{ .reg .u64 t; cvta.to.shared.u64 t, %1; cvt.u32.u64 %0, t; }"
        : "=r"(a) : "l"(p));
    return a;
}
__device__ __forceinline__ void cp_async16(uint32_t smem, const void* gmem) {
    asm volatile("cp.async.cg.shared.global [%0], [%1], 16;" :: "r"(smem), "l"(gmem));
}
#define CP_COMMIT() asm volatile("cp.async.commit_group;" ::: "memory")
#define CP_WAIT0()  asm volatile("cp.async.wait_group 0;" ::: "memory")

#define LDM_X4(r, addr) \
    asm volatile("ldmatrix.sync.aligned.m8n8.x4.shared.b16 {%0,%1,%2,%3}, [%4];" \
        : "=r"((r)[0]), "=r"((r)[1]), "=r"((r)[2]), "=r"((r)[3]) : "r"(addr))
// NON-trans x2: rows addressed by lanes 0-15; lane l gets M[l/4][2*(l%4)..+1]
#define LDM_X2(r0, r1, addr) \
    asm volatile("ldmatrix.sync.aligned.m8n8.x2.shared.b16 {%0,%1}, [%2];" \
        : "=r"(r0), "=r"(r1) : "r"(addr))
#define MMA_BF16(c, a, b0, b1) \
    asm volatile("mma.sync.aligned.m16n8k16.row.col.f32.bf16.bf16.f32 " \
        "{%0,%1,%2,%3}, {%4,%5,%6,%7}, {%8,%9}, {%0,%1,%2,%3};" \
        : "+f"((c)[0]), "+f"((c)[1]), "+f"((c)[2]), "+f"((c)[3]) \
        : "r"((a)[0]), "r"((a)[1]), "r"((a)[2]), "r"((a)[3]), "r"(b0), "r"(b1))

// ---------------- small kernels ----------------
__global__ void styles_kernel(const float* __restrict__ wvec,
                              const float* __restrict__ Aw,
                              const float* __restrict__ Ab,
                              float* __restrict__ outp) {
    const int b = blockIdx.y, wid = threadIdx.x >> 5, lane = threadIdx.x & 31;
    const int o = blockIdx.x * 8 + wid;
    const float* wp = wvec + b * LAT;
    const float* ap = Aw + (size_t)o * LAT;
    float acc = 0.f;
    #pragma unroll
    for (int it = 0; it < LAT / 32; it++) {
        int k = lane + 32 * it;
        acc += __ldg(&wp[k]) * __ldg(&ap[k]);
    }
    acc = warp_sum(acc);
    if (lane == 0) outp[b * CH + o] = acc + __ldg(&Ab[o]);
}
__global__ void wsq_kernel(const float* __restrict__ W, float* __restrict__ wq) {
    const int oi = blockIdx.x * 256 + threadIdx.x;
    const float* wp = W + (size_t)oi * 9;
    float s = 0.f;
    #pragma unroll
    for (int t = 0; t < 9; t++) { float v = __ldg(&wp[t]); s += v * v; }
    wq[oi] = s;
}
__global__ void rsigma_kernel(const float* __restrict__ style,
                              const float* __restrict__ wq,
                              float* __restrict__ rsig) {
    __shared__ float ss[CH];
    const int b = blockIdx.x, tid = threadIdx.x, wid = tid >> 5, lane = tid & 31;
    { float s = style[b * CH + tid]; ss[tid] = s * s; }
    __syncthreads();
    const int o0 = blockIdx.y * 32 + wid * 4;
    #pragma unroll
    for (int j = 0; j < 4; j++) {
        const int o = o0 + j;
        const float* qp = wq + (size_t)o * CH;
        float acc = 0.f;
        #pragma unroll
        for (int it = 0; it < CH / 32; it++)
            acc += ss[lane + 32 * it] * __ldg(&qp[lane + 32 * it]);
        acc = warp_sum(acc);
        if (lane == 0) rsig[b * CH + o] = rsqrtf(acc + 1e-8f);
    }
}

// ---------------- weight prep: W[256,256,3,3] -> ldmatrix-ready hi/lo -------
// stage st = (ocb*16 + chunk)*3 + ky; layout [kx][oc(128)][40] bf16 (80B rows)
// slots [0,16): Wh(ci = chunk*16+s), [16,32): Wl, [32,40): pad.
__global__ void wprep_kernel(const float* __restrict__ W,
                             unsigned short* __restrict__ wa) {
    size_t e = (size_t)blockIdx.x * 256 + threadIdx.x;   // < 96*15360
    int st = (int)(e / WA_STAGE_HALFS);
    int r  = (int)(e - (size_t)st * WA_STAGE_HALFS);
    int kx = r / 5120;  r -= kx * 5120;
    int oc = r / 40;
    int slot = r - oc * 40;
    int ocb = st / 48, s2 = st - ocb * 48;
    int chunk = s2 / 3, ky = s2 - chunk * 3;
    unsigned short outv = 0;
    if (slot < 32) {
        int ci = chunk * 16 + (slot & 15);
        float w = __ldg(&W[((size_t)(ocb * 128 + oc) * CH + ci) * 9 + ky * 3 + kx]);
        __nv_bfloat16 wh = __float2bfloat16(w);
        if (slot < 16) outv = __bfloat16_as_ushort(wh);
        else outv = __bfloat16_as_ushort(__float2bfloat16(w - __bfloat162float(wh)));
    }
    wa[e] = outv;
}

// ---------------- tensor-core conv kernel -----------------------------------
// CTA: 128 oc x 128 px (1 image row). 128 threads = 4 warps (warp 64x64).
// 2 CTAs co-resident per SM (reg- and smem-fitting) hide each other's syncs.
// smem: [0,1024) style | B slab 390 rows x 80B = 31200 | A dbuf 2 x 30720
#define SMB_OFF   1024
#define B_ROWS    390                       // 3 image rows x 130
#define SMA_OFF   (SMB_OFF + 31232)         // 32256 (aligned)
#define A_STAGE   30720
#define CONV_SMEM (SMA_OFF + 2 * A_STAGE)   // 93696

__global__ __launch_bounds__(128, 2)
void conv_mma_kernel(const float* __restrict__ in,
                     const unsigned short* __restrict__ wa,
                     const float* __restrict__ style,
                     const float* __restrict__ rsig,
                     const float* __restrict__ bias,
                     const float* __restrict__ ns,
                     const float* __restrict__ noise,
                     float* __restrict__ outp) {
    extern __shared__ unsigned char sm[];
    float* s_style = (float*)sm;
    unsigned char* smB = sm + SMB_OFF;
    const uint32_t smBu = smem_u32(smB);
    const uint32_t smAu = smem_u32(sm + SMA_OFF);

    const int tid  = threadIdx.x;
    const int wid  = tid >> 5;
    const int lane = tid & 31;
    const int wm   = wid & 1;        // oc half (64)
    const int wn   = wid >> 1;       // 0..1 -> x half (64)
    const int y0   = blockIdx.x;     // one image row per CTA
    const int ocb  = blockIdx.y;
    const int b    = blockIdx.z;

    for (int i = tid; i < CH; i += 128) s_style[i] = __ldg(&style[b * CH + i]);

    float acc[4][8][4];
    #pragma unroll
    for (int m = 0; m < 4; m++)
        #pragma unroll
        for (int n = 0; n < 8; n++)
            #pragma unroll
            for (int k = 0; k < 4; k++) acc[m][n][k] = 0.f;

    // lane-level ldmatrix address components (identical to R11)
    const uint32_t aLane = (uint32_t)(wm * 64 + (lane & 15)) * 80 + ((lane >> 4) * 16);
    const uint32_t bLane = (uint32_t)(lane & 7) * 80 + (((lane >> 3) & 1) * 16);

    const unsigned short* waBase = wa + (size_t)ocb * 48 * WA_STAGE_HALFS;

    auto stageA = [&](int st) {
        const unsigned char* src = (const unsigned char*)(waBase + (size_t)st * WA_STAGE_HALFS);
        uint32_t dst = smAu + (uint32_t)(st & 1) * A_STAGE;
        for (int i = tid; i < 1920; i += 128)
            cp_async16(dst + i * 16, src + (size_t)i * 16);
    };
    // build B(chunk): 3 slab rows x 130 px x 16 ci, hi/lo packed
    auto buildB = [&](int chunk) {
        for (int e = tid; e < 3120; e += 128) {
            int cl = e / 390;  int r = e - cl * 390;
            int rr = r / 130;  int pxi = r - rr * 130;
            int yi = y0 - 1 + rr, xi = pxi - 1;
            int ci = chunk * 16 + cl * 2;
            float v0 = 0.f, v1 = 0.f;
            if ((unsigned)yi < (unsigned)HW && (unsigned)xi < (unsigned)HW) {
                size_t base = ((size_t)(b * CH + ci) << 14) + (yi << 7) + xi;
                v0 = __ldg(&in[base]) * s_style[ci];
                v1 = __ldg(&in[base + (size_t)(1 << 14)]) * s_style[ci + 1];
            }
            __nv_bfloat16 h0 = __float2bfloat16(v0), h1 = __float2bfloat16(v1);
            __nv_bfloat16 l0 = __float2bfloat16(v0 - __bfloat162float(h0));
            __nv_bfloat16 l1 = __float2bfloat16(v1 - __bfloat162float(h1));
            uint32_t hh = ((uint32_t)__bfloat16_as_ushort(h1) << 16) | __bfloat16_as_ushort(h0);
            uint32_t ll = ((uint32_t)__bfloat16_as_ushort(l1) << 16) | __bfloat16_as_ushort(l0);
            int rp = rr * 130 + pxi;
            *(uint32_t*)(smB + rp * 80 + cl * 4)      = hh;   // k slots 2cl,2cl+1
            *(uint32_t*)(smB + rp * 80 + 32 + cl * 4) = ll;   // lo slots
        }
    };

    stageA(0); CP_COMMIT();

    #pragma unroll 1
    for (int st = 0; st < 48; st++) {
        const int chunk = st / 3, ky = st - chunk * 3;
        if (ky == 0) { __syncthreads(); buildB(chunk); }   // all prior readers done
        CP_WAIT0();              // A(st) landed (only group in flight)
        __syncthreads();         // B(chunk) + A(st) visible; st-1 readers done
        if (st + 1 < 48) { stageA(st + 1); CP_COMMIT(); }  // safe: buffer free now

        const uint32_t aBuf = smAu + (uint32_t)(st & 1) * A_STAGE;
        const int rr  = ky;                   // slab image-row for output y0
        const int x0w = wn * 64;

        #pragma unroll 1
        for (int kx = 0; kx < 3; kx++) {
            uint32_t a0[4][4], a1[4][4];      // Ah frags, Al frags
            #pragma unroll
            for (int m = 0; m < 4; m++) {
                uint32_t aa = aBuf + (uint32_t)kx * 10240 + (uint32_t)m * (16 * 80) + aLane;
                LDM_X4(a0[m], aa);
                LDM_X4(a1[m], aa + 32);
            }
            const uint32_t bRow0 = smBu + (uint32_t)(rr * 130 + x0w + kx) * 80 + bLane;
            #pragma unroll
            for (int n = 0; n < 8; n++) {
                uint32_t ba = bRow0 + (uint32_t)n * (8 * 80);
                uint32_t bh0, bh1, bl0, bl1;
                LDM_X2(bh0, bh1, ba);         // Bh (k 0-15)
                LDM_X2(bl0, bl1, ba + 32);    // Bl
                #pragma unroll
                for (int m = 0; m < 4; m++) MMA_BF16(acc[m][n], a0[m], bh0, bh1);
                #pragma unroll
                for (int m = 0; m < 4; m++) MMA_BF16(acc[m][n], a1[m], bh0, bh1);
                #pragma unroll
                for (int m = 0; m < 4; m++) MMA_BF16(acc[m][n], a0[m], bl0, bl1);
            }
        }
    }

    // ---- epilogue: demod + noise + bias + leaky relu ----
    const float nsv = __ldg(&ns[0]);
    const int y = y0;
    #pragma unroll
    for (int m = 0; m < 4; m++) {
        const int oc0 = ocb * 128 + wm * 64 + m * 16 + (lane >> 2);
        const float rs0 = __ldg(&rsig[b * CH + oc0]);
        const float rs1 = __ldg(&rsig[b * CH + oc0 + 8]);
        const float bj0 = __ldg(&bias[oc0]);
        const float bj1 = __ldg(&bias[oc0 + 8]);
        float* op0 = outp + ((size_t)(b * CH + oc0) << 14) + (y << 7);
        float* op1 = op0 + ((size_t)8 << 14);
        #pragma unroll
        for (int n = 0; n < 8; n++) {
            const int x = wn * 64 + n * 8 + 2 * (lane & 3);
            float2 nz = *(const float2*)(noise + ((size_t)b << 14) + (y << 7) + x);
            float v0 = acc[m][n][0] * rs0 + nsv * nz.x + bj0;
            float v1 = acc[m][n][1] * rs0 + nsv * nz.y + bj0;
            float v2 = acc[m][n][2] * rs1 + nsv * nz.x + bj1;
            float v3 = acc[m][n][3] * rs1 + nsv * nz.y + bj1;
            v0 = (v0 > 0.f) ? v0 : 0.2f * v0;
            v1 = (v1 > 0.f) ? v1 : 0.2f * v1;
            v2 = (v2 > 0.f) ? v2 : 0.2f * v2;
            v3 = (v3 > 0.f) ? v3 : 0.2f * v3;
            *(float2*)(op0 + x) = make_float2(v0, v1);
            *(float2*)(op1 + x) = make_float2(v2, v3);
        }
    }
}

// ---------------- RGB 1x1 modulated conv (no demod) ------------------------
__global__ void rgb_kernel(const float* __restrict__ out2,
                           const float* __restrict__ W3,
                           const float* __restrict__ style3,
                           float* __restrict__ rgb) {
    __shared__ float cf[3][CH];
    const int y = blockIdx.x, b = blockIdx.y, tid = threadIdx.x;
    for (int e = tid; e < 3 * CH; e += 128) {
        int rr = e >> 8, o = e & 255;
        cf[rr][o] = __ldg(&W3[rr * CH + o]) * style3[b * CH + o];
    }
    __syncthreads();
    const int x = tid;
    float a0 = 0.f, a1 = 0.f, a2 = 0.f;
    const float* base = out2 + ((size_t)(b * CH) << 14) + (y << 7) + x;
    #pragma unroll 8
    for (int o = 0; o < CH; o++) {
        float v = base[(size_t)o << 14];
        a0 += cf[0][o] * v; a1 += cf[1][o] * v; a2 += cf[2][o] * v;
    }
    const size_t px = ((size_t)y << 7) + x;
    rgb[((size_t)(b * 3 + 0) << 14) + px] = a0;
    rgb[((size_t)(b * 3 + 1) << 14) + px] = a1;
    rgb[((size_t)(b * 3 + 2) << 14) + px] = a2;
}

// ---------------------------------------------------------------------------
extern "C" void kernel_launch(void* const* d_in, const int* in_sizes, int n_in,
                              void* d_out, int out_size) {
    (void)in_sizes; (void)n_in; (void)out_size;
    const float* fm     = (const float*)d_in[0];
    const float* wv     = (const float*)d_in[1];
    const float* noise1 = (const float*)d_in[2];
    const float* noise2 = (const float*)d_in[3];
    const float* A1w    = (const float*)d_in[4];
    const float* A1b    = (const float*)d_in[5];
    const float* A2w    = (const float*)d_in[6];
    const float* A2b    = (const float*)d_in[7];
    const float* A3w    = (const float*)d_in[8];
    const float* A3b    = (const float*)d_in[9];
    const float* W1     = (const float*)d_in[10];
    const float* W2     = (const float*)d_in[11];
    const float* W3     = (const float*)d_in[12];
    const float* ns1    = (const float*)d_in[13];
    const float* ns2    = (const float*)d_in[14];
    const float* b1     = (const float*)d_in[15];
    const float* b2     = (const float*)d_in[16];

    float* out = (float*)d_out;
    float* rgb = out + (size_t)BATCH * CH * HW * HW;

    void *p_mid,*p_s1,*p_s2,*p_s3,*p_r1,*p_r2,*p_q1,*p_q2,*p_a1,*p_a2;
    cudaGetSymbolAddress(&p_mid, g_mid);
    cudaGetSymbolAddress(&p_s1, g_s1);
    cudaGetSymbolAddress(&p_s2, g_s2);
    cudaGetSymbolAddress(&p_s3, g_s3);
    cudaGetSymbolAddress(&p_r1, g_r1);
    cudaGetSymbolAddress(&p_r2, g_r2);
    cudaGetSymbolAddress(&p_q1, g_wq1);
    cudaGetSymbolAddress(&p_q2, g_wq2);
    cudaGetSymbolAddress(&p_a1, g_wa1);
    cudaGetSymbolAddress(&p_a2, g_wa2);
    float* mid = (float*)p_mid;
    float* s1 = (float*)p_s1; float* s2 = (float*)p_s2; float* s3 = (float*)p_s3;
    float* r1 = (float*)p_r1; float* r2 = (float*)p_r2;
    float* q1 = (float*)p_q1; float* q2 = (float*)p_q2;
    unsigned short* wa1 = (unsigned short*)p_a1;
    unsigned short* wa2 = (unsigned short*)p_a2;

    cudaFuncSetAttribute(conv_mma_kernel,
                         cudaFuncAttributeMaxDynamicSharedMemorySize, CONV_SMEM);

    dim3 cgrid(HW, 2, BATCH);   // 128 rows, 2 oc halves, 8 batches

    styles_kernel<<<dim3(CH / 8, BATCH), 256>>>(wv, A1w, A1b, s1);
    styles_kernel<<<dim3(CH / 8, BATCH), 256>>>(wv, A2w, A2b, s2);
    wsq_kernel<<<CH * CH / 256, 256>>>(W1, q1);
    rsigma_kernel<<<dim3(BATCH, CH / 32), 256>>>(s1, q1, r1);
    wprep_kernel<<<(int)(WA_HALFS / 256), 256>>>(W1, wa1);
    conv_mma_kernel<<<cgrid, 128, CONV_SMEM>>>(fm, wa1, s1, r1, b1,
                                               ns1, noise1, mid);
    styles_kernel<<<dim3(CH / 8, BATCH), 256>>>(wv, A3w, A3b, s3);
    wsq_kernel<<<CH * CH / 256, 256>>>(W2, q2);
    rsigma_kernel<<<dim3(BATCH, CH / 32), 256>>>(s2, q2, r2);
    wprep_kernel<<<(int)(WA_HALFS / 256), 256>>>(W2, wa2);
    conv_mma_kernel<<<cgrid, 128, CONV_SMEM>>>(mid, wa2, s2, r2, b2, ns2, noise2, out);
    rgb_kernel<<<dim3(HW, BATCH), 128>>>(out, W3, s3, rgb);
}

// round 15
// speedup vs baseline: 1.4051x; 1.2153x over previous
#include <cuda_runtime.h>
#include <cuda_fp16.h>
#include <cstddef>
#include <cstdint>

// ---------------------------------------------------------------------------
// StyleGAN2 block via legacy tensor cores (mma.sync m16n8k16 fp16, base PTX).
// Conv as implicit GEMM. R14 vs R13: fp16 hi/lo split on WEIGHTS only
// (2 MMAs per 16-ci group instead of 3; dropped term = W*(b-fp16(b)) ~2^-12)
// -> 1.5x less tensor work on an MMA-pipe-bound kernel. B build/ldmatrix halve.
// ---------------------------------------------------------------------------

#define BATCH 8
#define CH    256
#define HW    128
#define LAT   512

__device__ float g_mid[(size_t)BATCH * CH * HW * HW];   // conv1 output
__device__ float g_s1[BATCH * CH];
__device__ float g_s2[BATCH * CH];
__device__ float g_s3[BATCH * CH];
__device__ float g_r1[BATCH * CH];
__device__ float g_r2[BATCH * CH];
__device__ float g_wq1[CH * CH];
__device__ float g_wq2[CH * CH];
// rearranged weights: 96 stages x [kx(3)][oc(128)][40 slots] fp16  (2.95MB)
#define WA_STAGE_HALFS 15360            // 3*128*40
#define WA_HALFS ((size_t)96 * WA_STAGE_HALFS)
__device__ unsigned short g_wa1[WA_HALFS];
__device__ unsigned short g_wa2[WA_HALFS];

// ---------------- helpers ----------------
__device__ __forceinline__ float warp_sum(float v) {
    #pragma unroll
    for (int m = 16; m > 0; m >>= 1) v += __shfl_xor_sync(0xffffffffu, v, m);
    return v;
}
__device__ __forceinline__ uint32_t smem_u32(const void* p) {
    uint32_t a;
    asm("{ .reg .u64 t; cvta.to.shared.u64 t, %1; cvt.u32.u64 %0, t; }"
        : "=r"(a) : "l"(p));
    return a;
}
__device__ __forceinline__ void cp_async16(uint32_t smem, const void* gmem) {
    asm volatile("cp.async.cg.shared.global [%0], [%1], 16;" :: "r"(smem), "l"(gmem));
}
#define CP_COMMIT() asm volatile("cp.async.commit_group;" ::: "memory")
#define CP_WAIT0()  asm volatile("cp.async.wait_group 0;" ::: "memory")

#define LDM_X4(r, addr) \
    asm volatile("ldmatrix.sync.aligned.m8n8.x4.shared.b16 {%0,%1,%2,%3}, [%4];" \
        : "=r"((r)[0]), "=r"((r)[1]), "=r"((r)[2]), "=r"((r)[3]) : "r"(addr))
// NON-trans x2: rows addressed by lanes 0-15; lane l gets M[l/4][2*(l%4)..+1]
#define LDM_X2(r0, r1, addr) \
    asm volatile("ldmatrix.sync.aligned.m8n8.x2.shared.b16 {%0,%1}, [%2];" \
        : "=r"(r0), "=r"(r1) : "r"(addr))
#define MMA_F16(c, a, b0, b1) \
    asm volatile("mma.sync.aligned.m16n8k16.row.col.f32.f16.f16.f32 " \
        "{%0,%1,%2,%3}, {%4,%5,%6,%7}, {%8,%9}, {%0,%1,%2,%3};" \
        : "+f"((c)[0]), "+f"((c)[1]), "+f"((c)[2]), "+f"((c)[3]) \
        : "r"((a)[0]), "r"((a)[1]), "r"((a)[2]), "r"((a)[3]), "r"(b0), "r"(b1))

// ---------------- small kernels ----------------
__global__ void styles_kernel(const float* __restrict__ wvec,
                              const float* __restrict__ Aw,
                              const float* __restrict__ Ab,
                              float* __restrict__ outp) {
    const int b = blockIdx.y, wid = threadIdx.x >> 5, lane = threadIdx.x & 31;
    const int o = blockIdx.x * 8 + wid;
    const float* wp = wvec + b * LAT;
    const float* ap = Aw + (size_t)o * LAT;
    float acc = 0.f;
    #pragma unroll
    for (int it = 0; it < LAT / 32; it++) {
        int k = lane + 32 * it;
        acc += __ldg(&wp[k]) * __ldg(&ap[k]);
    }
    acc = warp_sum(acc);
    if (lane == 0) outp[b * CH + o] = acc + __ldg(&Ab[o]);
}

// fused: wq[o,i] = sum_t W^2  AND  wa = ldmatrix-ready fp16 hi/lo weights.
// wa stage st = (ocb*16 + chunk)*3 + ky; [kx][oc(128)][40] halfs (80B rows);
// slots [0,16): Wh(ci), [16,32): Wl(ci), [32,40): pad (zeroed by hi writes? no
// -> pad slots never read by ldmatrix (reads bytes [0,32) only), ok if garbage;
// but A ldmatrix DOES read [0,32) = exactly hi+lo, pad [32,40) untouched/unread)
__global__ void prep_kernel(const float* __restrict__ W,
                            unsigned short* __restrict__ wa,
                            float* __restrict__ wq) {
    int oi = blockIdx.x * 256 + threadIdx.x;   // o*256+ci, 65536 total
    int o = oi >> 8, ci = oi & 255;
    const float* wp = W + (size_t)oi * 9;
    float w[9]; float s = 0.f;
    #pragma unroll
    for (int t = 0; t < 9; t++) { w[t] = __ldg(&wp[t]); s += w[t] * w[t]; }
    wq[oi] = s;
    int ocb = o >> 7, ocl = o & 127;
    int chunk = ci >> 4, cil = ci & 15;
    #pragma unroll
    for (int ky = 0; ky < 3; ky++) {
        int st = (ocb * 16 + chunk) * 3 + ky;
        #pragma unroll
        for (int kx = 0; kx < 3; kx++) {
            float v = w[ky * 3 + kx];
            __half h = __float2half_rn(v);
            __half l = __float2half_rn(v - __half2float(h));
            size_t base = (size_t)st * WA_STAGE_HALFS + (size_t)kx * 5120 + ocl * 40;
            wa[base + cil]      = __half_as_ushort(h);
            wa[base + 16 + cil] = __half_as_ushort(l);
        }
    }
}

__global__ void rsigma_kernel(const float* __restrict__ style,
                              const float* __restrict__ wq,
                              float* __restrict__ rsig) {
    __shared__ float ss[CH];
    const int b = blockIdx.x, tid = threadIdx.x, wid = tid >> 5, lane = tid & 31;
    { float s = style[b * CH + tid]; ss[tid] = s * s; }
    __syncthreads();
    const int o0 = blockIdx.y * 32 + wid * 4;
    #pragma unroll
    for (int j = 0; j < 4; j++) {
        const int o = o0 + j;
        const float* qp = wq + (size_t)o * CH;
        float acc = 0.f;
        #pragma unroll
        for (int it = 0; it < CH / 32; it++)
            acc += ss[lane + 32 * it] * __ldg(&qp[lane + 32 * it]);
        acc = warp_sum(acc);
        if (lane == 0) rsig[b * CH + o] = rsqrtf(acc + 1e-8f);
    }
}

// ---------------- tensor-core conv kernel -----------------------------------
// CTA: 128 oc x 128 px (1 image row). 128 threads = 4 warps (warp 64x64).
// 2 CTAs co-resident per SM. smem: style | B slab (390x80B) | A dbuf 2x30720
#define SMB_OFF   1024
#define SMA_OFF   (SMB_OFF + 31232)         // 32256
#define A_STAGE   30720
#define CONV_SMEM (SMA_OFF + 2 * A_STAGE)   // 93696

__global__ __launch_bounds__(128, 2)
void conv_mma_kernel(const float* __restrict__ in,
                     const unsigned short* __restrict__ wa,
                     const float* __restrict__ style,
                     const float* __restrict__ rsig,
                     const float* __restrict__ bias,
                     const float* __restrict__ ns,
                     const float* __restrict__ noise,
                     float* __restrict__ outp) {
    extern __shared__ unsigned char sm[];
    float* s_style = (float*)sm;
    unsigned char* smB = sm + SMB_OFF;
    const uint32_t smBu = smem_u32(smB);
    const uint32_t smAu = smem_u32(sm + SMA_OFF);

    const int tid  = threadIdx.x;
    const int wid  = tid >> 5;
    const int lane = tid & 31;
    const int wm   = wid & 1;        // oc half (64)
    const int wn   = wid >> 1;       // 0..1 -> x half (64)
    const int y0   = blockIdx.x;     // one image row per CTA
    const int ocb  = blockIdx.y;
    const int b    = blockIdx.z;

    for (int i = tid; i < CH; i += 128) s_style[i] = __ldg(&style[b * CH + i]);

    float acc[4][8][4];
    #pragma unroll
    for (int m = 0; m < 4; m++)
        #pragma unroll
        for (int n = 0; n < 8; n++)
            #pragma unroll
            for (int k = 0; k < 4; k++) acc[m][n][k] = 0.f;

    // lane-level ldmatrix address components (verified in R11)
    const uint32_t aLane = (uint32_t)(wm * 64 + (lane & 15)) * 80 + ((lane >> 4) * 16);
    const uint32_t bLane = (uint32_t)(lane & 7) * 80 + (((lane >> 3) & 1) * 16);

    const unsigned short* waBase = wa + (size_t)ocb * 48 * WA_STAGE_HALFS;

    auto stageA = [&](int st) {
        const unsigned char* src = (const unsigned char*)(waBase + (size_t)st * WA_STAGE_HALFS);
        uint32_t dst = smAu + (uint32_t)(st & 1) * A_STAGE;
        for (int i = tid; i < 1920; i += 128)
            cp_async16(dst + i * 16, src + (size_t)i * 16);
    };
    // build B(chunk): 3 slab rows x 130 px x 16 ci, single fp16 (input*style)
    auto buildB = [&](int chunk) {
        for (int e = tid; e < 3120; e += 128) {
            int cl = e / 390;  int r = e - cl * 390;
            int rr = r / 130;  int pxi = r - rr * 130;
            int yi = y0 - 1 + rr, xi = pxi - 1;
            int ci = chunk * 16 + cl * 2;
            float v0 = 0.f, v1 = 0.f;
            if ((unsigned)yi < (unsigned)HW && (unsigned)xi < (unsigned)HW) {
                size_t base = ((size_t)(b * CH + ci) << 14) + (yi << 7) + xi;
                v0 = __ldg(&in[base]) * s_style[ci];
                v1 = __ldg(&in[base + (size_t)(1 << 14)]) * s_style[ci + 1];
            }
            __half h0 = __float2half_rn(v0), h1 = __float2half_rn(v1);
            uint32_t hh = ((uint32_t)__half_as_ushort(h1) << 16) | __half_as_ushort(h0);
            int rp = rr * 130 + pxi;
            *(uint32_t*)(smB + rp * 80 + cl * 4) = hh;   // k slots 2cl,2cl+1
        }
    };

    stageA(0); CP_COMMIT();

    #pragma unroll 1
    for (int st = 0; st < 48; st++) {
        const int chunk = st / 3, ky = st - chunk * 3;
        if (ky == 0) { __syncthreads(); buildB(chunk); }   // all prior readers done
        CP_WAIT0();              // A(st) landed (only group in flight)
        __syncthreads();         // B(chunk) + A(st) visible; st-1 readers done
        if (st + 1 < 48) { stageA(st + 1); CP_COMMIT(); }  // safe: buffer free now

        const uint32_t aBuf = smAu + (uint32_t)(st & 1) * A_STAGE;
        const int rr  = ky;                   // slab image-row for output y0
        const int x0w = wn * 64;

        #pragma unroll 1
        for (int kx = 0; kx < 3; kx++) {
            uint32_t a0[4][4], a1[4][4];      // Wh frags, Wl frags
            #pragma unroll
            for (int m = 0; m < 4; m++) {
                uint32_t aa = aBuf + (uint32_t)kx * 10240 + (uint32_t)m * (16 * 80) + aLane;
                LDM_X4(a0[m], aa);
                LDM_X4(a1[m], aa + 32);
            }
            const uint32_t bRow0 = smBu + (uint32_t)(rr * 130 + x0w + kx) * 80 + bLane;
            #pragma unroll
            for (int n = 0; n < 8; n++) {
                uint32_t ba = bRow0 + (uint32_t)n * (8 * 80);
                uint32_t bh0, bh1;
                LDM_X2(bh0, bh1, ba);         // Bh (k 0-15)
                #pragma unroll
                for (int m = 0; m < 4; m++) MMA_F16(acc[m][n], a0[m], bh0, bh1);
                #pragma unroll
                for (int m = 0; m < 4; m++) MMA_F16(acc[m][n], a1[m], bh0, bh1);
            }
        }
    }

    // ---- epilogue: demod + noise + bias + leaky relu ----
    const float nsv = __ldg(&ns[0]);
    const int y = y0;
    #pragma unroll
    for (int m = 0; m < 4; m++) {
        const int oc0 = ocb * 128 + wm * 64 + m * 16 + (lane >> 2);
        const float rs0 = __ldg(&rsig[b * CH + oc0]);
        const float rs1 = __ldg(&rsig[b * CH + oc0 + 8]);
        const float bj0 = __ldg(&bias[oc0]);
        const float bj1 = __ldg(&bias[oc0 + 8]);
        float* op0 = outp + ((size_t)(b * CH + oc0) << 14) + (y << 7);
        float* op1 = op0 + ((size_t)8 << 14);
        #pragma unroll
        for (int n = 0; n < 8; n++) {
            const int x = wn * 64 + n * 8 + 2 * (lane & 3);
            float2 nz = *(const float2*)(noise + ((size_t)b << 14) + (y << 7) + x);
            float v0 = acc[m][n][0] * rs0 + nsv * nz.x + bj0;
            float v1 = acc[m][n][1] * rs0 + nsv * nz.y + bj0;
            float v2 = acc[m][n][2] * rs1 + nsv * nz.x + bj1;
            float v3 = acc[m][n][3] * rs1 + nsv * nz.y + bj1;
            v0 = (v0 > 0.f) ? v0 : 0.2f * v0;
            v1 = (v1 > 0.f) ? v1 : 0.2f * v1;
            v2 = (v2 > 0.f) ? v2 : 0.2f * v2;
            v3 = (v3 > 0.f) ? v3 : 0.2f * v3;
            *(float2*)(op0 + x) = make_float2(v0, v1);
            *(float2*)(op1 + x) = make_float2(v2, v3);
        }
    }
}

// ---------------- RGB 1x1 modulated conv (no demod) ------------------------
__global__ void rgb_kernel(const float* __restrict__ out2,
                           const float* __restrict__ W3,
                           const float* __restrict__ style3,
                           float* __restrict__ rgb) {
    __shared__ float cf[3][CH];
    const int y = blockIdx.x, b = blockIdx.y, tid = threadIdx.x;
    for (int e = tid; e < 3 * CH; e += 128) {
        int rr = e >> 8, o = e & 255;
        cf[rr][o] = __ldg(&W3[rr * CH + o]) * style3[b * CH + o];
    }
    __syncthreads();
    const int x = tid;
    float a0 = 0.f, a1 = 0.f, a2 = 0.f;
    const float* base = out2 + ((size_t)(b * CH) << 14) + (y << 7) + x;
    #pragma unroll 8
    for (int o = 0; o < CH; o++) {
        float v = base[(size_t)o << 14];
        a0 += cf[0][o] * v; a1 += cf[1][o] * v; a2 += cf[2][o] * v;
    }
    const size_t px = ((size_t)y << 7) + x;
    rgb[((size_t)(b * 3 + 0) << 14) + px] = a0;
    rgb[((size_t)(b * 3 + 1) << 14) + px] = a1;
    rgb[((size_t)(b * 3 + 2) << 14) + px] = a2;
}

// ---------------------------------------------------------------------------
extern "C" void kernel_launch(void* const* d_in, const int* in_sizes, int n_in,
                              void* d_out, int out_size) {
    (void)in_sizes; (void)n_in; (void)out_size;
    const float* fm     = (const float*)d_in[0];
    const float* wv     = (const float*)d_in[1];
    const float* noise1 = (const float*)d_in[2];
    const float* noise2 = (const float*)d_in[3];
    const float* A1w    = (const float*)d_in[4];
    const float* A1b    = (const float*)d_in[5];
    const float* A2w    = (const float*)d_in[6];
    const float* A2b    = (const float*)d_in[7];
    const float* A3w    = (const float*)d_in[8];
    const float* A3b    = (const float*)d_in[9];
    const float* W1     = (const float*)d_in[10];
    const float* W2     = (const float*)d_in[11];
    const float* W3     = (const float*)d_in[12];
    const float* ns1    = (const float*)d_in[13];
    const float* ns2    = (const float*)d_in[14];
    const float* b1     = (const float*)d_in[15];
    const float* b2     = (const float*)d_in[16];

    float* out = (float*)d_out;
    float* rgb = out + (size_t)BATCH * CH * HW * HW;

    void *p_mid,*p_s1,*p_s2,*p_s3,*p_r1,*p_r2,*p_q1,*p_q2,*p_a1,*p_a2;
    cudaGetSymbolAddress(&p_mid, g_mid);
    cudaGetSymbolAddress(&p_s1, g_s1);
    cudaGetSymbolAddress(&p_s2, g_s2);
    cudaGetSymbolAddress(&p_s3, g_s3);
    cudaGetSymbolAddress(&p_r1, g_r1);
    cudaGetSymbolAddress(&p_r2, g_r2);
    cudaGetSymbolAddress(&p_q1, g_wq1);
    cudaGetSymbolAddress(&p_q2, g_wq2);
    cudaGetSymbolAddress(&p_a1, g_wa1);
    cudaGetSymbolAddress(&p_a2, g_wa2);
    float* mid = (float*)p_mid;
    float* s1 = (float*)p_s1; float* s2 = (float*)p_s2; float* s3 = (float*)p_s3;
    float* r1 = (float*)p_r1; float* r2 = (float*)p_r2;
    float* q1 = (float*)p_q1; float* q2 = (float*)p_q2;
    unsigned short* wa1 = (unsigned short*)p_a1;
    unsigned short* wa2 = (unsigned short*)p_a2;

    cudaFuncSetAttribute(conv_mma_kernel,
                         cudaFuncAttributeMaxDynamicSharedMemorySize, CONV_SMEM);

    dim3 cgrid(HW, 2, BATCH);   // 128 rows, 2 oc halves, 8 batches

    // conv1 placed early (observed ncu capture hits ~4th user launch)
    styles_kernel<<<dim3(CH / 8, BATCH), 256>>>(wv, A1w, A1b, s1);    // 1
    prep_kernel<<<CH * CH / 256, 256>>>(W1, wa1, q1);                 // 2
    rsigma_kernel<<<dim3(BATCH, CH / 32), 256>>>(s1, q1, r1);         // 3
    conv_mma_kernel<<<cgrid, 128, CONV_SMEM>>>(fm, wa1, s1, r1, b1,   // 4
                                               ns1, noise1, mid);
    styles_kernel<<<dim3(CH / 8, BATCH), 256>>>(wv, A2w, A2b, s2);
    prep_kernel<<<CH * CH / 256, 256>>>(W2, wa2, q2);
    rsigma_kernel<<<dim3(BATCH, CH / 32), 256>>>(s2, q2, r2);
    conv_mma_kernel<<<cgrid, 128, CONV_SMEM>>>(mid, wa2, s2, r2, b2, ns2, noise2, out);
    styles_kernel<<<dim3(CH / 8, BATCH), 256>>>(wv, A3w, A3b, s3);
    rgb_kernel<<<dim3(HW, BATCH), 128>>>(out, W3, s3, rgb);
}

// round 17
// speedup vs baseline: 1.7670x; 1.2576x over previous
#include <cuda_runtime.h>
#include <cuda_fp16.h>
#include <cstddef>
#include <cstdint>

// ---------------------------------------------------------------------------
// StyleGAN2 block via legacy tensor cores (mma.sync m16n8k16 fp16, base PTX).
// Conv as implicit GEMM; fp16 hi/lo split on weights (2 MMAs per 16-ci group).
// R16 vs R14: warp tile 64x64 -> 32x64 (8 warps / 256 threads per CTA,
// acc 128->64 regs) so 2 CTAs/SM = 16 warps/SM instead of 8 -> hide
// MMA/ldmatrix latency; ncu showed tensor=42%, occ=12%, regs=192.
// ---------------------------------------------------------------------------

#define BATCH 8
#define CH    256
#define HW    128
#define LAT   512

__device__ float g_mid[(size_t)BATCH * CH * HW * HW];   // conv1 output
__device__ float g_s1[BATCH * CH];
__device__ float g_s2[BATCH * CH];
__device__ float g_s3[BATCH * CH];
__device__ float g_r1[BATCH * CH];
__device__ float g_r2[BATCH * CH];
__device__ float g_wq1[CH * CH];
__device__ float g_wq2[CH * CH];
// rearranged weights: 96 stages x [kx(3)][oc(128)][40 slots] fp16  (2.95MB)
#define WA_STAGE_HALFS 15360            // 3*128*40
#define WA_HALFS ((size_t)96 * WA_STAGE_HALFS)
__device__ unsigned short g_wa1[WA_HALFS];
__device__ unsigned short g_wa2[WA_HALFS];

// ---------------- helpers ----------------
__device__ __forceinline__ float warp_sum(float v) {
    #pragma unroll
    for (int m = 16; m > 0; m >>= 1) v += __shfl_xor_sync(0xffffffffu, v, m);
    return v;
}
__device__ __forceinline__ uint32_t smem_u32(const void* p) {
    uint32_t a;
    asm("{ .reg .u64 t; cvta.to.shared.u64 t, %1; cvt.u32.u64 %0, t; }"
        : "=r"(a) : "l"(p));
    return a;
}
__device__ __forceinline__ void cp_async16(uint32_t smem, const void* gmem) {
    asm volatile("cp.async.cg.shared.global [%0], [%1], 16;" :: "r"(smem), "l"(gmem));
}
#define CP_COMMIT() asm volatile("cp.async.commit_group;" ::: "memory")
#define CP_WAIT0()  asm volatile("cp.async.wait_group 0;" ::: "memory")

#define LDM_X4(r, addr) \
    asm volatile("ldmatrix.sync.aligned.m8n8.x4.shared.b16 {%0,%1,%2,%3}, [%4];" \
        : "=r"((r)[0]), "=r"((r)[1]), "=r"((r)[2]), "=r"((r)[3]) : "r"(addr))
// NON-trans x2: rows addressed by lanes 0-15; lane l gets M[l/4][2*(l%4)..+1]
#define LDM_X2(r0, r1, addr) \
    asm volatile("ldmatrix.sync.aligned.m8n8.x2.shared.b16 {%0,%1}, [%2];" \
        : "=r"(r0), "=r"(r1) : "r"(addr))
#define MMA_F16(c, a, b0, b1) \
    asm volatile("mma.sync.aligned.m16n8k16.row.col.f32.f16.f16.f32 " \
        "{%0,%1,%2,%3}, {%4,%5,%6,%7}, {%8,%9}, {%0,%1,%2,%3};" \
        : "+f"((c)[0]), "+f"((c)[1]), "+f"((c)[2]), "+f"((c)[3]) \
        : "r"((a)[0]), "r"((a)[1]), "r"((a)[2]), "r"((a)[3]), "r"(b0), "r"(b1))

// ---------------- small kernels ----------------
__global__ void styles_kernel(const float* __restrict__ wvec,
                              const float* __restrict__ Aw,
                              const float* __restrict__ Ab,
                              float* __restrict__ outp) {
    const int b = blockIdx.y, wid = threadIdx.x >> 5, lane = threadIdx.x & 31;
    const int o = blockIdx.x * 8 + wid;
    const float* wp = wvec + b * LAT;
    const float* ap = Aw + (size_t)o * LAT;
    float acc = 0.f;
    #pragma unroll
    for (int it = 0; it < LAT / 32; it++) {
        int k = lane + 32 * it;
        acc += __ldg(&wp[k]) * __ldg(&ap[k]);
    }
    acc = warp_sum(acc);
    if (lane == 0) outp[b * CH + o] = acc + __ldg(&Ab[o]);
}

// fused: wq[o,i] = sum_t W^2  AND  wa = ldmatrix-ready fp16 hi/lo weights.
__global__ void prep_kernel(const float* __restrict__ W,
                            unsigned short* __restrict__ wa,
                            float* __restrict__ wq) {
    int oi = blockIdx.x * 256 + threadIdx.x;   // o*256+ci, 65536 total
    int o = oi >> 8, ci = oi & 255;
    const float* wp = W + (size_t)oi * 9;
    float w[9]; float s = 0.f;
    #pragma unroll
    for (int t = 0; t < 9; t++) { w[t] = __ldg(&wp[t]); s += w[t] * w[t]; }
    wq[oi] = s;
    int ocb = o >> 7, ocl = o & 127;
    int chunk = ci >> 4, cil = ci & 15;
    #pragma unroll
    for (int ky = 0; ky < 3; ky++) {
        int st = (ocb * 16 + chunk) * 3 + ky;
        #pragma unroll
        for (int kx = 0; kx < 3; kx++) {
            float v = w[ky * 3 + kx];
            __half h = __float2half_rn(v);
            __half l = __float2half_rn(v - __half2float(h));
            size_t base = (size_t)st * WA_STAGE_HALFS + (size_t)kx * 5120 + ocl * 40;
            wa[base + cil]      = __half_as_ushort(h);
            wa[base + 16 + cil] = __half_as_ushort(l);
        }
    }
}

__global__ void rsigma_kernel(const float* __restrict__ style,
                              const float* __restrict__ wq,
                              float* __restrict__ rsig) {
    __shared__ float ss[CH];
    const int b = blockIdx.x, tid = threadIdx.x, wid = tid >> 5, lane = tid & 31;
    { float s = style[b * CH + tid]; ss[tid] = s * s; }
    __syncthreads();
    const int o0 = blockIdx.y * 32 + wid * 4;
    #pragma unroll
    for (int j = 0; j < 4; j++) {
        const int o = o0 + j;
        const float* qp = wq + (size_t)o * CH;
        float acc = 0.f;
        #pragma unroll
        for (int it = 0; it < CH / 32; it++)
            acc += ss[lane + 32 * it] * __ldg(&qp[lane + 32 * it]);
        acc = warp_sum(acc);
        if (lane == 0) rsig[b * CH + o] = rsqrtf(acc + 1e-8f);
    }
}

// ---------------- tensor-core conv kernel -----------------------------------
// CTA: 128 oc x 128 px (1 image row). 256 threads = 8 warps, warp 32oc x 64px.
// 2 CTAs co-resident per SM -> 16 warps/SM.
// smem: [0,1024) style | B slab 390 rows x 80B | A dbuf 2 x 30720
#define SMB_OFF   1024
#define SMA_OFF   (SMB_OFF + 31232)         // 32256
#define A_STAGE   30720
#define CONV_SMEM (SMA_OFF + 2 * A_STAGE)   // 93696

__global__ __launch_bounds__(256, 2)
void conv_mma_kernel(const float* __restrict__ in,
                     const unsigned short* __restrict__ wa,
                     const float* __restrict__ style,
                     const float* __restrict__ rsig,
                     const float* __restrict__ bias,
                     const float* __restrict__ ns,
                     const float* __restrict__ noise,
                     float* __restrict__ outp) {
    extern __shared__ unsigned char sm[];
    float* s_style = (float*)sm;
    unsigned char* smB = sm + SMB_OFF;
    const uint32_t smBu = smem_u32(smB);
    const uint32_t smAu = smem_u32(sm + SMA_OFF);

    const int tid  = threadIdx.x;
    const int wid  = tid >> 5;
    const int lane = tid & 31;
    const int wm   = wid & 3;        // oc quarter (32 oc)
    const int wn   = wid >> 2;       // 0..1 -> x half (64 px)
    const int y0   = blockIdx.x;     // one image row per CTA
    const int ocb  = blockIdx.y;
    const int b    = blockIdx.z;

    for (int i = tid; i < CH; i += 256) s_style[i] = __ldg(&style[b * CH + i]);

    float acc[2][8][4];
    #pragma unroll
    for (int m = 0; m < 2; m++)
        #pragma unroll
        for (int n = 0; n < 8; n++)
            #pragma unroll
            for (int k = 0; k < 4; k++) acc[m][n][k] = 0.f;

    // lane-level ldmatrix address components (R11-verified mapping)
    const uint32_t aLane = (uint32_t)(wm * 32 + (lane & 15)) * 80 + ((lane >> 4) * 16);
    const uint32_t bLane = (uint32_t)(lane & 7) * 80 + (((lane >> 3) & 1) * 16);

    const unsigned short* waBase = wa + (size_t)ocb * 48 * WA_STAGE_HALFS;

    auto stageA = [&](int st) {
        const unsigned char* src = (const unsigned char*)(waBase + (size_t)st * WA_STAGE_HALFS);
        uint32_t dst = smAu + (uint32_t)(st & 1) * A_STAGE;
        for (int i = tid; i < 1920; i += 256)
            cp_async16(dst + i * 16, src + (size_t)i * 16);
    };
    // build B(chunk): 3 slab rows x 130 px x 16 ci, single fp16 (input*style)
    auto buildB = [&](int chunk) {
        for (int e = tid; e < 3120; e += 256) {
            int cl = e / 390;  int r = e - cl * 390;
            int rr = r / 130;  int pxi = r - rr * 130;
            int yi = y0 - 1 + rr, xi = pxi - 1;
            int ci = chunk * 16 + cl * 2;
            float v0 = 0.f, v1 = 0.f;
            if ((unsigned)yi < (unsigned)HW && (unsigned)xi < (unsigned)HW) {
                size_t base = ((size_t)(b * CH + ci) << 14) + (yi << 7) + xi;
                v0 = __ldg(&in[base]) * s_style[ci];
                v1 = __ldg(&in[base + (size_t)(1 << 14)]) * s_style[ci + 1];
            }
            __half h0 = __float2half_rn(v0), h1 = __float2half_rn(v1);
            uint32_t hh = ((uint32_t)__half_as_ushort(h1) << 16) | __half_as_ushort(h0);
            int rp = rr * 130 + pxi;
            *(uint32_t*)(smB + rp * 80 + cl * 4) = hh;   // k slots 2cl,2cl+1
        }
    };

    stageA(0); CP_COMMIT();

    #pragma unroll 1
    for (int st = 0; st < 48; st++) {
        const int chunk = st / 3, ky = st - chunk * 3;
        if (ky == 0) { __syncthreads(); buildB(chunk); }   // all prior readers done
        CP_WAIT0();              // A(st) landed (only group in flight)
        __syncthreads();         // B(chunk) + A(st) visible; st-1 readers done
        if (st + 1 < 48) { stageA(st + 1); CP_COMMIT(); }  // safe: buffer free now

        const uint32_t aBuf = smAu + (uint32_t)(st & 1) * A_STAGE;
        const int rr  = ky;                   // slab image-row for output y0
        const int x0w = wn * 64;

        #pragma unroll 1
        for (int kx = 0; kx < 3; kx++) {
            uint32_t a0[2][4], a1[2][4];      // Wh frags, Wl frags (2 m-tiles)
            #pragma unroll
            for (int m = 0; m < 2; m++) {
                uint32_t aa = aBuf + (uint32_t)kx * 10240 + (uint32_t)m * (16 * 80) + aLane;
                LDM_X4(a0[m], aa);
                LDM_X4(a1[m], aa + 32);
            }
            const uint32_t bRow0 = smBu + (uint32_t)(rr * 130 + x0w + kx) * 80 + bLane;
            #pragma unroll
            for (int n = 0; n < 8; n++) {
                uint32_t ba = bRow0 + (uint32_t)n * (8 * 80);
                uint32_t bh0, bh1;
                LDM_X2(bh0, bh1, ba);         // Bh (k 0-15)
                #pragma unroll
                for (int m = 0; m < 2; m++) MMA_F16(acc[m][n], a0[m], bh0, bh1);
                #pragma unroll
                for (int m = 0; m < 2; m++) MMA_F16(acc[m][n], a1[m], bh0, bh1);
            }
        }
    }

    // ---- epilogue: demod + noise + bias + leaky relu ----
    const float nsv = __ldg(&ns[0]);
    const int y = y0;
    #pragma unroll
    for (int m = 0; m < 2; m++) {
        const int oc0 = ocb * 128 + wm * 32 + m * 16 + (lane >> 2);
        const float rs0 = __ldg(&rsig[b * CH + oc0]);
        const float rs1 = __ldg(&rsig[b * CH + oc0 + 8]);
        const float bj0 = __ldg(&bias[oc0]);
        const float bj1 = __ldg(&bias[oc0 + 8]);
        float* op0 = outp + ((size_t)(b * CH + oc0) << 14) + (y << 7);
        float* op1 = op0 + ((size_t)8 << 14);
        #pragma unroll
        for (int n = 0; n < 8; n++) {
            const int x = wn * 64 + n * 8 + 2 * (lane & 3);
            float2 nz = *(const float2*)(noise + ((size_t)b << 14) + (y << 7) + x);
            float v0 = acc[m][n][0] * rs0 + nsv * nz.x + bj0;
            float v1 = acc[m][n][1] * rs0 + nsv * nz.y + bj0;
            float v2 = acc[m][n][2] * rs1 + nsv * nz.x + bj1;
            float v3 = acc[m][n][3] * rs1 + nsv * nz.y + bj1;
            v0 = (v0 > 0.f) ? v0 : 0.2f * v0;
            v1 = (v1 > 0.f) ? v1 : 0.2f * v1;
            v2 = (v2 > 0.f) ? v2 : 0.2f * v2;
            v3 = (v3 > 0.f) ? v3 : 0.2f * v3;
            *(float2*)(op0 + x) = make_float2(v0, v1);
            *(float2*)(op1 + x) = make_float2(v2, v3);
        }
    }
}

// ---------------- RGB 1x1 modulated conv (no demod) ------------------------
__global__ void rgb_kernel(const float* __restrict__ out2,
                           const float* __restrict__ W3,
                           const float* __restrict__ style3,
                           float* __restrict__ rgb) {
    __shared__ float cf[3][CH];
    const int y = blockIdx.x, b = blockIdx.y, tid = threadIdx.x;
    for (int e = tid; e < 3 * CH; e += 128) {
        int rr = e >> 8, o = e & 255;
        cf[rr][o] = __ldg(&W3[rr * CH + o]) * style3[b * CH + o];
    }
    __syncthreads();
    const int x = tid;
    float a0 = 0.f, a1 = 0.f, a2 = 0.f;
    const float* base = out2 + ((size_t)(b * CH) << 14) + (y << 7) + x;
    #pragma unroll 8
    for (int o = 0; o < CH; o++) {
        float v = base[(size_t)o << 14];
        a0 += cf[0][o] * v; a1 += cf[1][o] * v; a2 += cf[2][o] * v;
    }
    const size_t px = ((size_t)y << 7) + x;
    rgb[((size_t)(b * 3 + 0) << 14) + px] = a0;
    rgb[((size_t)(b * 3 + 1) << 14) + px] = a1;
    rgb[((size_t)(b * 3 + 2) << 14) + px] = a2;
}

// ---------------------------------------------------------------------------
extern "C" void kernel_launch(void* const* d_in, const int* in_sizes, int n_in,
                              void* d_out, int out_size) {
    (void)in_sizes; (void)n_in; (void)out_size;
    const float* fm     = (const float*)d_in[0];
    const float* wv     = (const float*)d_in[1];
    const float* noise1 = (const float*)d_in[2];
    const float* noise2 = (const float*)d_in[3];
    const float* A1w    = (const float*)d_in[4];
    const float* A1b    = (const float*)d_in[5];
    const float* A2w    = (const float*)d_in[6];
    const float* A2b    = (const float*)d_in[7];
    const float* A3w    = (const float*)d_in[8];
    const float* A3b    = (const float*)d_in[9];
    const float* W1     = (const float*)d_in[10];
    const float* W2     = (const float*)d_in[11];
    const float* W3     = (const float*)d_in[12];
    const float* ns1    = (const float*)d_in[13];
    const float* ns2    = (const float*)d_in[14];
    const float* b1     = (const float*)d_in[15];
    const float* b2     = (const float*)d_in[16];

    float* out = (float*)d_out;
    float* rgb = out + (size_t)BATCH * CH * HW * HW;

    void *p_mid,*p_s1,*p_s2,*p_s3,*p_r1,*p_r2,*p_q1,*p_q2,*p_a1,*p_a2;
    cudaGetSymbolAddress(&p_mid, g_mid);
    cudaGetSymbolAddress(&p_s1, g_s1);
    cudaGetSymbolAddress(&p_s2, g_s2);
    cudaGetSymbolAddress(&p_s3, g_s3);
    cudaGetSymbolAddress(&p_r1, g_r1);
    cudaGetSymbolAddress(&p_r2, g_r2);
    cudaGetSymbolAddress(&p_q1, g_wq1);
    cudaGetSymbolAddress(&p_q2, g_wq2);
    cudaGetSymbolAddress(&p_a1, g_wa1);
    cudaGetSymbolAddress(&p_a2, g_wa2);
    float* mid = (float*)p_mid;
    float* s1 = (float*)p_s1; float* s2 = (float*)p_s2; float* s3 = (float*)p_s3;
    float* r1 = (float*)p_r1; float* r2 = (float*)p_r2;
    float* q1 = (float*)p_q1; float* q2 = (float*)p_q2;
    unsigned short* wa1 = (unsigned short*)p_a1;
    unsigned short* wa2 = (unsigned short*)p_a2;

    cudaFuncSetAttribute(conv_mma_kernel,
                         cudaFuncAttributeMaxDynamicSharedMemorySize, CONV_SMEM);

    dim3 cgrid(HW, 2, BATCH);   // 128 rows, 2 oc halves, 8 batches

    // conv1 kept as 4th launch (ncu -s 5 -c 1 captured it in R15)
    styles_kernel<<<dim3(CH / 8, BATCH), 256>>>(wv, A1w, A1b, s1);    // 1
    prep_kernel<<<CH * CH / 256, 256>>>(W1, wa1, q1);                 // 2
    rsigma_kernel<<<dim3(BATCH, CH / 32), 256>>>(s1, q1, r1);         // 3
    conv_mma_kernel<<<cgrid, 256, CONV_SMEM>>>(fm, wa1, s1, r1, b1,   // 4
                                               ns1, noise1, mid);
    styles_kernel<<<dim3(CH / 8, BATCH), 256>>>(wv, A2w, A2b, s2);
    prep_kernel<<<CH * CH / 256, 256>>>(W2, wa2, q2);
    rsigma_kernel<<<dim3(BATCH, CH / 32), 256>>>(s2, q2, r2);
    conv_mma_kernel<<<cgrid, 256, CONV_SMEM>>>(mid, wa2, s2, r2, b2, ns2, noise2, out);
    styles_kernel<<<dim3(CH / 8, BATCH), 256>>>(wv, A3w, A3b, s3);
    rgb_kernel<<<dim3(HW, BATCH), 128>>>(out, W3, s3, rgb);
}